// round 2
// baseline (speedup 1.0000x reference)
#include <cuda_runtime.h>
#include <cuda_bf16.h>
#include <mma.h>
#include <math.h>

using namespace nvcuda;

// Problem shape (fixed): T=256, B=64, D=H=1024
#define TT 256
#define BB 64
#define HH 1024
#define NG 4096      // 4*H
#define TBm 16384    // T*B

// ---------------- scratch (device globals: allocation-free rule) -------------
__device__ float g_zx[(size_t)TBm * NG];     // 256 MB: x-projection for current layer
__device__ float g_hall[(size_t)TBm * HH];   // 64 MB: layer-0 hidden sequence
__device__ float g_h0[BB * HH];              // zero h for t=0
__device__ float g_c[BB * HH];               // cell state (in-place per layer)

// ---------------- helpers ----------------------------------------------------
__device__ __forceinline__ void split_bf16(float x, __nv_bfloat16& hi, __nv_bfloat16& lo) {
    hi = __float2bfloat16(x);
    lo = __float2bfloat16(x - __bfloat162float(hi));
}
__device__ __forceinline__ float sigmoidf_(float x) { return 1.0f / (1.0f + expf(-x)); }

__global__ void zero2_kernel(float* a, float* b, int n) {
    int i = blockIdx.x * blockDim.x + threadIdx.x;
    if (i < n) { a[i] = 0.0f; b[i] = 0.0f; }
}

// ---------------- big input-projection GEMM ----------------------------------
// Z[M,4096] = A[M,1024] @ W[1024,4096]   (bias folded into step kernel)
// BM=128, BN=128, BK=32; 256 threads = 8 warps (2 x 4), warp tile 64x32.
// bf16 hi/lo 3-pass emulated-fp32 MMA.
#define GBM 128
#define GBN 128
#define GBK 32

__global__ __launch_bounds__(256) void gemm_x_kernel(
    const float* __restrict__ A, const float* __restrict__ W,
    float* __restrict__ Z)
{
    __shared__ __nv_bfloat16 Ah[GBM][GBK + 8];
    __shared__ __nv_bfloat16 Al[GBM][GBK + 8];
    __shared__ __nv_bfloat16 Bh[GBK][GBN + 8];
    __shared__ __nv_bfloat16 Bl[GBK][GBN + 8];

    const int bm = blockIdx.y * GBM;
    const int bn = blockIdx.x * GBN;
    const int tid = threadIdx.x;
    const int warp = tid >> 5;
    const int wm = (warp >> 2) * 64;   // warp row offset in tile
    const int wn = (warp & 3) * 32;    // warp col offset in tile

    wmma::fragment<wmma::accumulator, 16, 16, 16, float> acc[4][2];
#pragma unroll
    for (int i = 0; i < 4; ++i)
#pragma unroll
        for (int j = 0; j < 2; ++j)
            wmma::fill_fragment(acc[i][j], 0.0f);

    for (int kb = 0; kb < HH; kb += GBK) {
        // load A tile 128x32 (1024 quads, 4 per thread)
#pragma unroll
        for (int i = 0; i < 4; ++i) {
            int q = tid + i * 256;
            int r = q >> 3, c = (q & 7) * 4;
            float4 v = *(const float4*)(A + (size_t)(bm + r) * HH + kb + c);
            split_bf16(v.x, Ah[r][c + 0], Al[r][c + 0]);
            split_bf16(v.y, Ah[r][c + 1], Al[r][c + 1]);
            split_bf16(v.z, Ah[r][c + 2], Al[r][c + 2]);
            split_bf16(v.w, Ah[r][c + 3], Al[r][c + 3]);
        }
        // load B tile 32x128 (1024 quads, 4 per thread)
#pragma unroll
        for (int i = 0; i < 4; ++i) {
            int q = tid + i * 256;
            int r = q >> 5, c = (q & 31) * 4;
            float4 v = *(const float4*)(W + (size_t)(kb + r) * NG + bn + c);
            split_bf16(v.x, Bh[r][c + 0], Bl[r][c + 0]);
            split_bf16(v.y, Bh[r][c + 1], Bl[r][c + 1]);
            split_bf16(v.z, Bh[r][c + 2], Bl[r][c + 2]);
            split_bf16(v.w, Bh[r][c + 3], Bl[r][c + 3]);
        }
        __syncthreads();

#pragma unroll
        for (int kk = 0; kk < GBK; kk += 16) {
            wmma::fragment<wmma::matrix_a, 16, 16, 16, __nv_bfloat16, wmma::row_major> ah[4], al[4];
            wmma::fragment<wmma::matrix_b, 16, 16, 16, __nv_bfloat16, wmma::row_major> bh[2], bl[2];
#pragma unroll
            for (int i = 0; i < 4; ++i) {
                wmma::load_matrix_sync(ah[i], &Ah[wm + 16 * i][kk], GBK + 8);
                wmma::load_matrix_sync(al[i], &Al[wm + 16 * i][kk], GBK + 8);
            }
#pragma unroll
            for (int j = 0; j < 2; ++j) {
                wmma::load_matrix_sync(bh[j], &Bh[kk][wn + 16 * j], GBN + 8);
                wmma::load_matrix_sync(bl[j], &Bl[kk][wn + 16 * j], GBN + 8);
            }
#pragma unroll
            for (int i = 0; i < 4; ++i)
#pragma unroll
                for (int j = 0; j < 2; ++j) {
                    wmma::mma_sync(acc[i][j], ah[i], bh[j], acc[i][j]);
                    wmma::mma_sync(acc[i][j], ah[i], bl[j], acc[i][j]);
                    wmma::mma_sync(acc[i][j], al[i], bh[j], acc[i][j]);
                }
        }
        __syncthreads();
    }

#pragma unroll
    for (int i = 0; i < 4; ++i)
#pragma unroll
        for (int j = 0; j < 2; ++j)
            wmma::store_matrix_sync(Z + (size_t)(bm + wm + 16 * i) * NG + bn + wn + 16 * j,
                                    acc[i][j], NG, wmma::mem_row_major);
}

// ---------------- fused recurrent step ---------------------------------------
// CTA j handles gate-columns [j*16, j*16+16) of H.
// Warp g computes z_g[64,16] = hin[64,1024] @ Wh[:, g*1024 + nj .. +16], then all
// threads fuse gates: new_c = c*sig(f+1) + sig(i)*tanh(j); new_h = tanh(c)*sig(o).
#define SBK 32

__global__ __launch_bounds__(128) void lstm_step_kernel(
    const float* __restrict__ zx,    // [64,4096] for this t (has x@Wx, no bias)
    const float* __restrict__ Wh,    // [1024,4096]
    const float* __restrict__ bias,  // [4096]
    const float* __restrict__ hin,   // [64,1024]  (previous h)
    float* __restrict__ cst,         // [64,1024]  cell state (in/out)
    float* __restrict__ hout)        // [64,1024]  new h
{
    __shared__ __nv_bfloat16 Hh[64][SBK + 8];
    __shared__ __nv_bfloat16 Hl[64][SBK + 8];
    __shared__ __nv_bfloat16 Wsh[SBK][64 + 8];
    __shared__ __nv_bfloat16 Wsl[SBK][64 + 8];
    __shared__ float zs[4][64][16];

    const int tid = threadIdx.x;   // 128
    const int warp = tid >> 5;     // gate id 0..3
    const int nj = blockIdx.x * 16;

    wmma::fragment<wmma::accumulator, 16, 16, 16, float> acc[4];
#pragma unroll
    for (int i = 0; i < 4; ++i) wmma::fill_fragment(acc[i], 0.0f);

    for (int kb = 0; kb < HH; kb += SBK) {
        // H tile 64x32: 512 quads, 4 per thread
#pragma unroll
        for (int i = 0; i < 4; ++i) {
            int q = tid + i * 128;
            int r = q >> 3, c = (q & 7) * 4;
            float4 v = *(const float4*)(hin + (size_t)r * HH + kb + c);
            split_bf16(v.x, Hh[r][c + 0], Hl[r][c + 0]);
            split_bf16(v.y, Hh[r][c + 1], Hl[r][c + 1]);
            split_bf16(v.z, Hh[r][c + 2], Hl[r][c + 2]);
            split_bf16(v.w, Hh[r][c + 3], Hl[r][c + 3]);
        }
        // W tile 32 rows x 64 cols (4 gates x 16): 512 quads, 4 per thread
#pragma unroll
        for (int i = 0; i < 4; ++i) {
            int q = tid + i * 128;
            int r = q >> 4;
            int cq = q & 15;           // quad-in-row; col = cq*4 = gate*16 + (cc)
            int gate = cq >> 2, cc = (cq & 3) * 4;
            float4 v = *(const float4*)(Wh + (size_t)(kb + r) * NG + gate * HH + nj + cc);
            int col = cq * 4;
            split_bf16(v.x, Wsh[r][col + 0], Wsl[r][col + 0]);
            split_bf16(v.y, Wsh[r][col + 1], Wsl[r][col + 1]);
            split_bf16(v.z, Wsh[r][col + 2], Wsl[r][col + 2]);
            split_bf16(v.w, Wsh[r][col + 3], Wsl[r][col + 3]);
        }
        __syncthreads();

#pragma unroll
        for (int kk = 0; kk < SBK; kk += 16) {
            wmma::fragment<wmma::matrix_b, 16, 16, 16, __nv_bfloat16, wmma::row_major> bh, bl;
            wmma::load_matrix_sync(bh, &Wsh[kk][warp * 16], 64 + 8);
            wmma::load_matrix_sync(bl, &Wsl[kk][warp * 16], 64 + 8);
#pragma unroll
            for (int i = 0; i < 4; ++i) {
                wmma::fragment<wmma::matrix_a, 16, 16, 16, __nv_bfloat16, wmma::row_major> ah, al;
                wmma::load_matrix_sync(ah, &Hh[16 * i][kk], SBK + 8);
                wmma::load_matrix_sync(al, &Hl[16 * i][kk], SBK + 8);
                wmma::mma_sync(acc[i], ah, bh, acc[i]);
                wmma::mma_sync(acc[i], ah, bl, acc[i]);
                wmma::mma_sync(acc[i], al, bh, acc[i]);
            }
        }
        __syncthreads();
    }

    // park recurrent z in shared, then fuse gates
#pragma unroll
    for (int i = 0; i < 4; ++i)
        wmma::store_matrix_sync(&zs[warp][16 * i][0], acc[i], 16, wmma::mem_row_major);
    __syncthreads();

#pragma unroll
    for (int e = tid; e < 64 * 16; e += 128) {
        int r = e >> 4, col = e & 15;
        int gc = nj + col;
        const float* zr = zx + (size_t)r * NG;
        float zi = zs[0][r][col] + zr[gc]            + bias[gc];
        float zj = zs[1][r][col] + zr[HH + gc]       + bias[HH + gc];
        float zf = zs[2][r][col] + zr[2 * HH + gc]   + bias[2 * HH + gc];
        float zo = zs[3][r][col] + zr[3 * HH + gc]   + bias[3 * HH + gc];
        float cold = cst[(size_t)r * HH + gc];
        float nc = cold * sigmoidf_(zf + 1.0f) + sigmoidf_(zi) * tanhf(zj);
        float nh = tanhf(nc) * sigmoidf_(zo);
        cst[(size_t)r * HH + gc] = nc;
        hout[(size_t)r * HH + gc] = nh;
    }
}

// ---------------- launch ------------------------------------------------------
extern "C" void kernel_launch(void* const* d_in, const int* in_sizes, int n_in,
                              void* d_out, int out_size)
{
    const float* x  = (const float*)d_in[0];   // [256,64,1024]
    const float* W0 = (const float*)d_in[1];   // [2048,4096]
    const float* b0 = (const float*)d_in[2];   // [4096]
    const float* W1 = (const float*)d_in[3];   // [2048,4096]
    const float* b1 = (const float*)d_in[4];   // [4096]
    float* out = (float*)d_out;                // [256,64,1024]

    float *zx, *hall, *h0, *cst;
    cudaGetSymbolAddress((void**)&zx,   g_zx);
    cudaGetSymbolAddress((void**)&hall, g_hall);
    cudaGetSymbolAddress((void**)&h0,   g_h0);
    cudaGetSymbolAddress((void**)&cst,  g_c);

    const dim3 ggrid(NG / GBN, TBm / GBM);   // (32, 128)

    // ---- layer 0 ----
    zero2_kernel<<<(BB * HH + 255) / 256, 256>>>(h0, cst, BB * HH);
    gemm_x_kernel<<<ggrid, 256>>>(x, W0, zx);
    for (int t = 0; t < TT; ++t) {
        const float* hin = (t == 0) ? h0 : (hall + (size_t)(t - 1) * BB * HH);
        lstm_step_kernel<<<HH / 16, 128>>>(zx + (size_t)t * BB * NG,
                                           W0 + (size_t)HH * NG, b0,
                                           hin, cst, hall + (size_t)t * BB * HH);
    }

    // ---- layer 1 ----
    zero2_kernel<<<(BB * HH + 255) / 256, 256>>>(h0, cst, BB * HH);
    gemm_x_kernel<<<ggrid, 256>>>(hall, W1, zx);
    for (int t = 0; t < TT; ++t) {
        const float* hin = (t == 0) ? h0 : (out + (size_t)(t - 1) * BB * HH);
        lstm_step_kernel<<<HH / 16, 128>>>(zx + (size_t)t * BB * NG,
                                           W1 + (size_t)HH * NG, b1,
                                           hin, cst, out + (size_t)t * BB * HH);
    }
}